// round 2
// baseline (speedup 1.0000x reference)
#include <cuda_runtime.h>
#include <math.h>

#define BDIM 128
#define NDIM 20000
#define DDIM 3072
#define KB 16
#define NSPLIT 8
#define NCHUNK (NDIM / NSPLIT)        /* 2500 */
#define NTILES ((NDIM + 127) / 128)   /* 157 */
#define DTILES (DDIM / 128)           /* 24 */

// Scratch (allocation-free rule: __device__ globals)
__device__ float g_s[BDIM * NDIM];               // scaled logits, 10.24 MB
__device__ float g_rowmax[BDIM];
__device__ float g_rowsum[BDIM];
__device__ float g_part[NSPLIT * BDIM * DDIM];   // GEMM2 split-K partials, 12.6 MB

// ---------------------------------------------------------------------------
// GEMM1: s[b,n] = alpha[b] * (x_b . gt_n) - beta[b] * ||gt_n||^2
// alpha = tt/sig^2, beta = 0.5*tt^2/sig^2  (per-row constants of log_p drop
// out of softmax, including the reference's global-max shift).
// Tile: 128 B-rows x 128 N-cols, K over D=3072.
// ---------------------------------------------------------------------------
__global__ __launch_bounds__(256) void gemm1_kernel(const float* __restrict__ x,
                                                    const float* __restrict__ t,
                                                    const float* __restrict__ gt)
{
    __shared__ float As[KB][BDIM];   // x transposed: As[k][b]
    __shared__ float Bs[KB][BDIM];   // gt transposed: Bs[k][n]
    __shared__ float g2s[BDIM];

    const int tid  = threadIdx.x;
    const int nblk = blockIdx.x * 128;
    const int r0 = (tid >> 4) << 3;     // output row group (b)
    const int c0 = (tid & 15) << 3;     // output col group (n)

    const int lrow = tid >> 2;          // 0..63 (loads rows lrow, lrow+64)
    const int lk   = (tid & 3) << 2;    // 0,4,8,12

    float acc[8][8];
#pragma unroll
    for (int i = 0; i < 8; i++)
#pragma unroll
        for (int j = 0; j < 8; j++) acc[i][j] = 0.0f;
    float g2a[8] = {0, 0, 0, 0, 0, 0, 0, 0};

    const float* xr0 = x + (size_t)lrow * DDIM + lk;
    const float* xr1 = x + (size_t)(lrow + 64) * DDIM + lk;
    const int n0g = nblk + lrow;
    const int n1g = nblk + lrow + 64;
    const float* gr0 = gt + (size_t)n0g * DDIM + lk;
    const float* gr1 = gt + (size_t)n1g * DDIM + lk;
    const bool v0 = (n0g < NDIM);
    const bool v1 = (n1g < NDIM);
    const float4 zero4 = make_float4(0.f, 0.f, 0.f, 0.f);

    for (int k0 = 0; k0 < DDIM; k0 += KB) {
        float4 a0 = *(const float4*)(xr0 + k0);
        float4 a1 = *(const float4*)(xr1 + k0);
        float4 b0 = v0 ? *(const float4*)(gr0 + k0) : zero4;
        float4 b1 = v1 ? *(const float4*)(gr1 + k0) : zero4;

        __syncthreads();
        As[lk + 0][lrow] = a0.x; As[lk + 1][lrow] = a0.y;
        As[lk + 2][lrow] = a0.z; As[lk + 3][lrow] = a0.w;
        As[lk + 0][lrow + 64] = a1.x; As[lk + 1][lrow + 64] = a1.y;
        As[lk + 2][lrow + 64] = a1.z; As[lk + 3][lrow + 64] = a1.w;
        Bs[lk + 0][lrow] = b0.x; Bs[lk + 1][lrow] = b0.y;
        Bs[lk + 2][lrow] = b0.z; Bs[lk + 3][lrow] = b0.w;
        Bs[lk + 0][lrow + 64] = b1.x; Bs[lk + 1][lrow + 64] = b1.y;
        Bs[lk + 2][lrow + 64] = b1.z; Bs[lk + 3][lrow + 64] = b1.w;
        __syncthreads();

#pragma unroll
        for (int k = 0; k < KB; k++) {
            float a[8], b[8];
#pragma unroll
            for (int i = 0; i < 8; i++) a[i] = As[k][r0 + i];
#pragma unroll
            for (int j = 0; j < 8; j++) b[j] = Bs[k][c0 + j];
            if (tid < 16) {          // r0==0 threads own each n-column once
#pragma unroll
                for (int j = 0; j < 8; j++) g2a[j] += b[j] * b[j];
            }
#pragma unroll
            for (int i = 0; i < 8; i++)
#pragma unroll
                for (int j = 0; j < 8; j++) acc[i][j] += a[i] * b[j];
        }
    }

    if (tid < 16) {
#pragma unroll
        for (int j = 0; j < 8; j++) g2s[c0 + j] = g2a[j];
    }
    __syncthreads();

    float g2l[8];
#pragma unroll
    for (int j = 0; j < 8; j++) g2l[j] = g2s[c0 + j];

#pragma unroll
    for (int i = 0; i < 8; i++) {
        const int b = r0 + i;
        const float tt  = t[b] * (1.0f / 999.0f);
        const float sg  = 1.0f - tt;
        const float inv = 1.0f / (sg * sg);
        const float alpha = tt * inv;
        const float beta  = 0.5f * tt * tt * inv;
#pragma unroll
        for (int j = 0; j < 8; j++) {
            const int n = nblk + c0 + j;
            if (n < NDIM)
                g_s[b * NDIM + n] = alpha * acc[i][j] - beta * g2l[j];
        }
    }
}

// ---------------------------------------------------------------------------
// Per-row softmax stats: rowmax and sum(exp(s - rowmax)). One block per row.
// ---------------------------------------------------------------------------
__global__ __launch_bounds__(256) void softmax_stats_kernel()
{
    const int b   = blockIdx.x;
    const int tid = threadIdx.x;
    const float* row = g_s + (size_t)b * NDIM;
    __shared__ float red[256];

    float m = -INFINITY;
    for (int i = tid; i < NDIM; i += 256) m = fmaxf(m, row[i]);
    red[tid] = m;
    __syncthreads();
    for (int s = 128; s > 0; s >>= 1) {
        if (tid < s) red[tid] = fmaxf(red[tid], red[tid + s]);
        __syncthreads();
    }
    m = red[0];
    __syncthreads();

    float sum = 0.0f;
    for (int i = tid; i < NDIM; i += 256) sum += __expf(row[i] - m);
    red[tid] = sum;
    __syncthreads();
    for (int s = 128; s > 0; s >>= 1) {
        if (tid < s) red[tid] += red[tid + s];
        __syncthreads();
    }
    if (tid == 0) {
        g_rowmax[b] = m;
        g_rowsum[b] = red[0];
    }
}

// ---------------------------------------------------------------------------
// GEMM2: partial[b,d] = sum_{n in split} eta[b,n] * gt[n,d]
// eta materialized on the fly from g_s. Split-K over N into NSPLIT partials
// (deterministic, no atomics). Tile 128 B x 128 D, K over n-chunk of 2500.
// ---------------------------------------------------------------------------
__global__ __launch_bounds__(256) void gemm2_kernel(const float* __restrict__ gt)
{
    __shared__ float Es[KB][BDIM];   // eta transposed: Es[kn][b]
    __shared__ float Gs[KB][BDIM];   // gt tile: Gs[kn][d]

    const int tid  = threadIdx.x;
    const int dblk = blockIdx.x * 128;
    const int nbeg = blockIdx.y * NCHUNK;
    const int nend = nbeg + NCHUNK;
    const int r0 = (tid >> 4) << 3;
    const int c0 = (tid & 15) << 3;

    // eta loads: rows lrow, lrow+64 (b); 4 n's at lk
    const int lrow = tid >> 2;
    const int lk   = (tid & 3) << 2;
    // gt loads: rows gn, gn+8 (n); float4 at gd
    const int gn = tid >> 5;            // 0..7
    const int gd = (tid & 31) << 2;     // 0..124

    const float m0  = g_rowmax[lrow];
    const float is0 = 1.0f / g_rowsum[lrow];
    const float m1  = g_rowmax[lrow + 64];
    const float is1 = 1.0f / g_rowsum[lrow + 64];

    const float4 zero4 = make_float4(0.f, 0.f, 0.f, 0.f);

    float acc[8][8];
#pragma unroll
    for (int i = 0; i < 8; i++)
#pragma unroll
        for (int j = 0; j < 8; j++) acc[i][j] = 0.0f;

    for (int n0 = nbeg; n0 < nend; n0 += KB) {
        // eta tile (scalar guarded loads; g_s is L2-resident)
        float e0[4], e1[4];
#pragma unroll
        for (int c = 0; c < 4; c++) {
            const int n = n0 + lk + c;
            if (n < nend) {
                e0[c] = __expf(g_s[lrow * NDIM + n] - m0) * is0;
                e1[c] = __expf(g_s[(lrow + 64) * NDIM + n] - m1) * is1;
            } else {
                e0[c] = 0.0f;
                e1[c] = 0.0f;
            }
        }
        // gt tile
        const int nr0 = n0 + gn, nr1 = n0 + gn + 8;
        float4 gv0 = (nr0 < nend) ? *(const float4*)(gt + (size_t)nr0 * DDIM + dblk + gd) : zero4;
        float4 gv1 = (nr1 < nend) ? *(const float4*)(gt + (size_t)nr1 * DDIM + dblk + gd) : zero4;

        __syncthreads();
#pragma unroll
        for (int c = 0; c < 4; c++) {
            Es[lk + c][lrow]      = e0[c];
            Es[lk + c][lrow + 64] = e1[c];
        }
        Gs[gn][gd + 0] = gv0.x; Gs[gn][gd + 1] = gv0.y;
        Gs[gn][gd + 2] = gv0.z; Gs[gn][gd + 3] = gv0.w;
        Gs[gn + 8][gd + 0] = gv1.x; Gs[gn + 8][gd + 1] = gv1.y;
        Gs[gn + 8][gd + 2] = gv1.z; Gs[gn + 8][gd + 3] = gv1.w;
        __syncthreads();

#pragma unroll
        for (int k = 0; k < KB; k++) {
            float a[8], b[8];
#pragma unroll
            for (int i = 0; i < 8; i++) a[i] = Es[k][r0 + i];
#pragma unroll
            for (int j = 0; j < 8; j++) b[j] = Gs[k][c0 + j];
#pragma unroll
            for (int i = 0; i < 8; i++)
#pragma unroll
                for (int j = 0; j < 8; j++) acc[i][j] += a[i] * b[j];
        }
    }

    float* outp = g_part + (size_t)blockIdx.y * BDIM * DDIM;
#pragma unroll
    for (int i = 0; i < 8; i++)
#pragma unroll
        for (int j = 0; j < 8; j++)
            outp[(r0 + i) * DDIM + dblk + c0 + j] = acc[i][j];
}

// ---------------------------------------------------------------------------
// Epilogue: out = (sum_splits partial - x) / sig
// ---------------------------------------------------------------------------
__global__ __launch_bounds__(256) void epilogue_kernel(const float* __restrict__ x,
                                                       const float* __restrict__ t,
                                                       float* __restrict__ out)
{
    const int idx = blockIdx.x * 256 + threadIdx.x;
    if (idx >= BDIM * DDIM) return;
    const int b = idx / DDIM;
    float a = 0.0f;
#pragma unroll
    for (int s = 0; s < NSPLIT; s++) a += g_part[(size_t)s * BDIM * DDIM + idx];
    const float tt = t[b] * (1.0f / 999.0f);
    const float sg = 1.0f - tt;
    out[idx] = (a - x[idx]) / sg;
}

extern "C" void kernel_launch(void* const* d_in, const int* in_sizes, int n_in,
                              void* d_out, int out_size)
{
    const float* xt = (const float*)d_in[0];
    const float* t  = (const float*)d_in[1];
    const float* gt = (const float*)d_in[2];
    float* out = (float*)d_out;

    gemm1_kernel<<<NTILES, 256>>>(xt, t, gt);
    softmax_stats_kernel<<<BDIM, 256>>>();
    dim3 g3(DTILES, NSPLIT);
    gemm2_kernel<<<g3, 256>>>(gt);
    epilogue_kernel<<<(BDIM * DDIM + 255) / 256, 256>>>(xt, t, out);
}